// round 5
// baseline (speedup 1.0000x reference)
#include <cuda_runtime.h>
#include <cuda_bf16.h>
#include <cstdint>

// Problem constants
constexpr int B  = 8;
constexpr int S  = 4096;
constexpr int D  = 64;
constexpr int DS = 16;
constexpr int CH = 64;                       // chunk length (tokens)
constexpr int NCHUNKS = B * S / CH;          // 512
constexpr int NTOK = B * S;                  // 32768

// Scratch (static __device__ globals: allowed; no runtime allocation)
__device__ float g_A [NTOK * DS * DS];       // 33.5 MB : per-token A matrices
__device__ float g_Bx[NTOK * DS];            //  2  MB : per-token Bx vectors
__device__ float g_P [NCHUNKS * DS * DS];    // chunk transition matrices
__device__ float g_q [NCHUNKS * DS];         // chunk offset vectors
__device__ float g_H0[NCHUNKS * DS];         // state at each chunk start

// ---------------------------------------------------------------------------
// K1: per chunk — compute A_t, Bx_t for 64 tokens, then fold chunk into (P, q)
// smem: sx[64*64] sA[64*256] sBx[64*16] sP[2*256] sq[2*16]  = 88192 B
// ---------------------------------------------------------------------------
__global__ __launch_bounds__(256)
void k1_proj_scan(const float* __restrict__ x,
                  const float* __restrict__ WA, const float* __restrict__ bA,
                  const float* __restrict__ WB, const float* __restrict__ bB)
{
    extern __shared__ float sm[];
    float* sx  = sm;                 // 64*64
    float* sA  = sx  + 64 * 64;      // 64*256
    float* sBx = sA  + 64 * 256;     // 64*16
    float* sP  = sBx + 64 * 16;      // 2*256
    float* sq  = sP  + 512;          // 2*16

    const int c   = blockIdx.x;      // chunk id, 0..511 (tiles B*S contiguously)
    const int tid = threadIdx.x;
    const float* xc = x + (size_t)c * CH * D;

    // load x chunk (4096 floats) as float4
    {
        const float4* src = (const float4*)xc;
        float4* dst = (float4*)sx;
        for (int i = tid; i < (CH * D) / 4; i += 256) dst[i] = src[i];
    }
    __syncthreads();

    // ---- Phase A: A = x @ W_A + b_A. Thread owns column i for all 64 tokens.
    {
        const int i = tid;           // 0..255
        const float bias = bA[i];
        for (int half = 0; half < 2; ++half) {
            float acc[32];
            #pragma unroll
            for (int t = 0; t < 32; ++t) acc[t] = bias;
            for (int k4 = 0; k4 < 16; ++k4) {
                const float w0 = WA[(k4 * 4 + 0) * 256 + i];
                const float w1 = WA[(k4 * 4 + 1) * 256 + i];
                const float w2 = WA[(k4 * 4 + 2) * 256 + i];
                const float w3 = WA[(k4 * 4 + 3) * 256 + i];
                #pragma unroll
                for (int t = 0; t < 32; ++t) {
                    float4 xv = *(const float4*)&sx[(half * 32 + t) * 64 + k4 * 4];
                    acc[t] += xv.x * w0 + xv.y * w1 + xv.z * w2 + xv.w * w3;
                }
            }
            #pragma unroll
            for (int t = 0; t < 32; ++t) {
                const int tok = half * 32 + t;
                sA[tok * 256 + i] = acc[t];
                g_A[((size_t)c * CH + tok) * 256 + i] = acc[t];
            }
        }
    }

    // ---- Phase B: Bx[t,n] = sum_d (x@W_B + b_B)[t,n,d] * x[t,d]
    // thread: n = tid>>4, d-quad dq = tid&15; 8-token tiles
    {
        const int n  = tid >> 4;
        const int dq = tid & 15;
        const float4 bb = *(const float4*)&bB[n * 64 + dq * 4];
        for (int tt = 0; tt < 8; ++tt) {
            float4 bm[8];
            #pragma unroll
            for (int t = 0; t < 8; ++t) bm[t] = bb;
            for (int k = 0; k < 64; ++k) {
                const float4 w = *(const float4*)&WB[k * 1024 + n * 64 + dq * 4];
                #pragma unroll
                for (int t = 0; t < 8; ++t) {
                    const float xk = sx[(tt * 8 + t) * 64 + k];
                    bm[t].x += xk * w.x; bm[t].y += xk * w.y;
                    bm[t].z += xk * w.z; bm[t].w += xk * w.w;
                }
            }
            #pragma unroll
            for (int t = 0; t < 8; ++t) {
                const int tok = tt * 8 + t;
                const float4 xd = *(const float4*)&sx[tok * 64 + dq * 4];
                float v = bm[t].x * xd.x + bm[t].y * xd.y + bm[t].z * xd.z + bm[t].w * xd.w;
                v += __shfl_xor_sync(0xffffffffu, v, 8, 16);
                v += __shfl_xor_sync(0xffffffffu, v, 4, 16);
                v += __shfl_xor_sync(0xffffffffu, v, 2, 16);
                v += __shfl_xor_sync(0xffffffffu, v, 1, 16);
                if (dq == 0) {
                    sBx[tok * 16 + n] = v;
                    g_Bx[((size_t)c * CH + tok) * 16 + n] = v;
                }
            }
        }
    }

    // ---- Phase C: chunk scan — P <- A_t P, q <- A_t q + Bx_t (t = 0..63)
    {
        const int pi = tid >> 4, pj = tid & 15;
        sP[tid]       = (pi == pj) ? 1.0f : 0.0f;
        sP[256 + tid] = 0.0f;
        if (tid < 16) { sq[tid] = 0.0f; sq[16 + tid] = 0.0f; }
        __syncthreads();

        int cur = 0;
        for (int t = 0; t < CH; ++t) {
            const float* At = &sA[t * 256];
            float np = 0.0f;
            #pragma unroll
            for (int k = 0; k < 16; ++k)
                np += At[pi * 16 + k] * sP[cur * 256 + k * 16 + pj];
            float nq = 0.0f;
            if (tid < 16) {
                nq = sBx[t * 16 + tid];
                #pragma unroll
                for (int k = 0; k < 16; ++k)
                    nq += At[tid * 16 + k] * sq[cur * 16 + k];
            }
            sP[(cur ^ 1) * 256 + tid] = np;
            if (tid < 16) sq[(cur ^ 1) * 16 + tid] = nq;
            cur ^= 1;
            __syncthreads();
        }
        g_P[c * 256 + tid] = sP[cur * 256 + tid];
        if (tid < 16) g_q[c * 16 + tid] = sq[cur * 16 + tid];
    }
}

// ---------------------------------------------------------------------------
// K2: per batch — serial scan over 64 chunk pairs -> g_H0 (state at chunk start)
// smem: cP[64*256] cq[64*16] = 69632 B
// ---------------------------------------------------------------------------
__global__ __launch_bounds__(256)
void k2_chain(void)
{
    extern __shared__ float sm[];
    float* cP = sm;            // 64*256
    float* cq = cP + 64 * 256; // 64*16

    const int b   = blockIdx.x;    // 0..7
    const int tid = threadIdx.x;

    for (int e = tid; e < 64 * 256; e += 256) cP[e] = g_P[b * 64 * 256 + e];
    for (int e = tid; e < 64 * 16;  e += 256) cq[e] = g_q[b * 64 * 16 + e];
    __syncthreads();

    if (tid < 32) {
        const int i = tid & 15;
        float h = 0.0f;
        for (int cc = 0; cc < 64; ++cc) {
            if (tid < 16) g_H0[(b * 64 + cc) * 16 + i] = h;
            float acc = cq[cc * 16 + i];
            #pragma unroll
            for (int j = 0; j < 16; ++j) {
                const float hj = __shfl_sync(0xffffffffu, h, j);
                acc += cP[cc * 256 + i * 16 + j] * hj;
            }
            h = acc;
        }
    }
}

// ---------------------------------------------------------------------------
// K3: per chunk — replay recurrence from g_H0, then out = (x@W_C + b_C)^T h
// smem: sx[64*68] sA[64*256] sBx[64*16] sh[64*16] = 91136 B
// ---------------------------------------------------------------------------
constexpr int SXS = 68;  // padded x row stride (bank-conflict-free in output loop)

__global__ __launch_bounds__(256)
void k3_replay_out(const float* __restrict__ x,
                   const float* __restrict__ WC, const float* __restrict__ bC,
                   float* __restrict__ out)
{
    extern __shared__ float sm[];
    float* sx  = sm;                 // 64*68
    float* sA  = sx  + 64 * SXS;     // 64*256
    float* sBx = sA  + 64 * 256;     // 64*16
    float* sh  = sBx + 64 * 16;      // 64*16

    const int c   = blockIdx.x;
    const int tid = threadIdx.x;
    const float* xc = x + (size_t)c * CH * D;

    // load x (scalar, strided layout), A chunk (float4), Bx chunk
    for (int i = tid; i < CH * D; i += 256) {
        const int t = i >> 6, k = i & 63;
        sx[t * SXS + k] = xc[i];
    }
    {
        const float4* src = (const float4*)(g_A + (size_t)c * CH * 256);
        float4* dst = (float4*)sA;
        for (int i = tid; i < (CH * 256) / 4; i += 256) dst[i] = src[i];
    }
    for (int i = tid; i < CH * 16; i += 256) sBx[i] = g_Bx[(size_t)c * CH * 16 + i];
    __syncthreads();

    // replay: warp 0 only (lanes duplicated i = lane&15)
    if (tid < 32) {
        const int i = tid & 15;
        float h = g_H0[c * 16 + i];
        for (int t = 0; t < CH; ++t) {
            float acc = sBx[t * 16 + i];
            #pragma unroll
            for (int j = 0; j < 16; ++j) {
                const float hj = __shfl_sync(0xffffffffu, h, j);
                acc += sA[t * 256 + i * 16 + j] * hj;
            }
            h = acc;
            if (tid < 16) sh[t * 16 + i] = h;
        }
    }
    __syncthreads();

    // output: thread owns 4 tokens x 4 d's.  dq = tid&15, tg = tid>>4
    {
        const int dq = tid & 15;
        const int tg = tid >> 4;              // 16 groups of 4 tokens
        const float4 bc = *(const float4*)&bC[0 * 64 + dq * 4]; // per-n below
        (void)bc;
        float4 oacc[4];
        #pragma unroll
        for (int t = 0; t < 4; ++t) oacc[t] = make_float4(0.f, 0.f, 0.f, 0.f);

        for (int n = 0; n < 16; ++n) {
            const float4 bcn = *(const float4*)&bC[n * 64 + dq * 4];
            float4 cm[4];
            #pragma unroll
            for (int t = 0; t < 4; ++t) cm[t] = bcn;
            for (int k = 0; k < 64; ++k) {
                const float4 w = *(const float4*)&WC[k * 1024 + n * 64 + dq * 4];
                #pragma unroll
                for (int t = 0; t < 4; ++t) {
                    const float xk = sx[(tg * 4 + t) * SXS + k];
                    cm[t].x += xk * w.x; cm[t].y += xk * w.y;
                    cm[t].z += xk * w.z; cm[t].w += xk * w.w;
                }
            }
            #pragma unroll
            for (int t = 0; t < 4; ++t) {
                const float hn = sh[(tg * 4 + t) * 16 + n];
                oacc[t].x += hn * cm[t].x; oacc[t].y += hn * cm[t].y;
                oacc[t].z += hn * cm[t].z; oacc[t].w += hn * cm[t].w;
            }
        }
        #pragma unroll
        for (int t = 0; t < 4; ++t) {
            const int tok = tg * 4 + t;
            *(float4*)&out[((size_t)c * CH + tok) * 64 + dq * 4] = oacc[t];
        }
    }
}

// ---------------------------------------------------------------------------
extern "C" void kernel_launch(void* const* d_in, const int* in_sizes, int n_in,
                              void* d_out, int out_size)
{
    const float* x  = (const float*)d_in[0];
    const float* WA = (const float*)d_in[1];
    const float* bA = (const float*)d_in[2];
    const float* WB = (const float*)d_in[3];
    const float* bB = (const float*)d_in[4];
    const float* WC = (const float*)d_in[5];
    const float* bC = (const float*)d_in[6];
    float* out = (float*)d_out;

    const int smem1 = (64 * 64 + 64 * 256 + 64 * 16 + 512 + 32) * 4;        // 88192
    const int smem2 = (64 * 256 + 64 * 16) * 4;                             // 69632
    const int smem3 = (64 * SXS + 64 * 256 + 64 * 16 + 64 * 16) * 4;        // 91136

    cudaFuncSetAttribute(k1_proj_scan,  cudaFuncAttributeMaxDynamicSharedMemorySize, smem1);
    cudaFuncSetAttribute(k2_chain,      cudaFuncAttributeMaxDynamicSharedMemorySize, smem2);
    cudaFuncSetAttribute(k3_replay_out, cudaFuncAttributeMaxDynamicSharedMemorySize, smem3);

    k1_proj_scan <<<NCHUNKS, 256, smem1>>>(x, WA, bA, WB, bB);
    k2_chain     <<<B,       256, smem2>>>();
    k3_replay_out<<<NCHUNKS, 256, smem3>>>(x, WC, bC, out);
}

// round 7
// speedup vs baseline: 1.1299x; 1.1299x over previous
#include <cuda_runtime.h>
#include <cuda_bf16.h>
#include <cstdint>

// Problem constants
constexpr int B  = 8;
constexpr int S  = 4096;
constexpr int D  = 64;
constexpr int DS = 16;
constexpr int CH = 64;                       // chunk length (tokens)
constexpr int NCHUNKS = B * S / CH;          // 512
constexpr int NTOK = B * S;                  // 32768

// Scratch (static __device__ globals: allowed; no runtime allocation)
// Per-token within-chunk prefix transition Pref_t = A_t...A_0 and offset r_t,
// so h_t = Pref_t @ h0(chunk) + r_t  (no serial replay needed downstream).
__device__ float g_Pref[NTOK * DS * DS];     // 33.5 MB
__device__ float g_r  [NTOK * DS];           //  2  MB
__device__ float g_H0 [NCHUNKS * DS];        // state at each chunk start

// ---------------------------------------------------------------------------
// K1: per chunk — A projection, Bx, then chunk scan emitting ALL prefixes
// smem: sx[64*64] sA[64*256] sBx[64*16] sP[2*256] sq[2*16]  = 88192 B
// ---------------------------------------------------------------------------
__global__ __launch_bounds__(256, 2)
void k1_proj_scan(const float* __restrict__ x,
                  const float* __restrict__ WA, const float* __restrict__ bA,
                  const float* __restrict__ WB, const float* __restrict__ bB)
{
    extern __shared__ float sm[];
    float* sx  = sm;                 // 64*64
    float* sA  = sx  + 64 * 64;      // 64*256
    float* sBx = sA  + 64 * 256;     // 64*16
    float* sP  = sBx + 64 * 16;      // 2*256
    float* sq  = sP  + 512;          // 2*16

    const int c   = blockIdx.x;
    const int tid = threadIdx.x;
    const float* xc = x + (size_t)c * CH * D;

    // load x chunk (4096 floats) as float4
    {
        const float4* src = (const float4*)xc;
        float4* dst = (float4*)sx;
        for (int i = tid; i < (CH * D) / 4; i += 256) dst[i] = src[i];
    }
    __syncthreads();

    // ---- Phase A: A = x @ W_A + b_A. Thread owns column i for all 64 tokens.
    //      Prefetched weight quad hides the LDG latency behind 128 FMAs.
    {
        const int i = tid;           // 0..255
        const float bias = bA[i];
        for (int half = 0; half < 2; ++half) {
            float acc[32];
            #pragma unroll
            for (int t = 0; t < 32; ++t) acc[t] = bias;
            float w0 = WA[0 * 256 + i], w1 = WA[1 * 256 + i];
            float w2 = WA[2 * 256 + i], w3 = WA[3 * 256 + i];
            for (int k4 = 0; k4 < 16; ++k4) {
                const int nk = (k4 < 15) ? (k4 + 1) * 4 : 0;
                const float n0 = WA[(nk + 0) * 256 + i];
                const float n1 = WA[(nk + 1) * 256 + i];
                const float n2 = WA[(nk + 2) * 256 + i];
                const float n3 = WA[(nk + 3) * 256 + i];
                #pragma unroll
                for (int t = 0; t < 32; ++t) {
                    float4 xv = *(const float4*)&sx[(half * 32 + t) * 64 + k4 * 4];
                    acc[t] += xv.x * w0 + xv.y * w1 + xv.z * w2 + xv.w * w3;
                }
                w0 = n0; w1 = n1; w2 = n2; w3 = n3;
            }
            #pragma unroll
            for (int t = 0; t < 32; ++t)
                sA[(half * 32 + t) * 256 + i] = acc[t];
        }
    }

    // ---- Phase B: Bx[t,n] = sum_d (x@W_B + b_B)[t,n,d] * x[t,d]
    //      thread: n = tid>>4, d-quad dq = tid&15; 8-token tiles; W_B prefetched.
    {
        const int n  = tid >> 4;
        const int dq = tid & 15;
        const float4 bb = *(const float4*)&bB[n * 64 + dq * 4];
        const float4* WB4 = (const float4*)WB;
        const int widx = n * 16 + dq;           // float4 column index (of 256)
        for (int tt = 0; tt < 8; ++tt) {
            float4 bm[8];
            #pragma unroll
            for (int t = 0; t < 8; ++t) bm[t] = bb;
            float4 w[4];
            #pragma unroll
            for (int j = 0; j < 4; ++j) w[j] = WB4[j * 256 + widx];
            for (int kg = 0; kg < 16; ++kg) {
                float4 wn[4];
                const int nk = (kg < 15) ? (kg + 1) * 4 : 0;
                #pragma unroll
                for (int j = 0; j < 4; ++j) wn[j] = WB4[(nk + j) * 256 + widx];
                #pragma unroll
                for (int j = 0; j < 4; ++j) {
                    const int k = kg * 4 + j;
                    #pragma unroll
                    for (int t = 0; t < 8; ++t) {
                        const float xk = sx[(tt * 8 + t) * 64 + k];
                        bm[t].x += xk * w[j].x; bm[t].y += xk * w[j].y;
                        bm[t].z += xk * w[j].z; bm[t].w += xk * w[j].w;
                    }
                }
                #pragma unroll
                for (int j = 0; j < 4; ++j) w[j] = wn[j];
            }
            #pragma unroll
            for (int t = 0; t < 8; ++t) {
                const int tok = tt * 8 + t;
                const float4 xd = *(const float4*)&sx[tok * 64 + dq * 4];
                float v = bm[t].x * xd.x + bm[t].y * xd.y + bm[t].z * xd.z + bm[t].w * xd.w;
                v += __shfl_xor_sync(0xffffffffu, v, 8, 16);
                v += __shfl_xor_sync(0xffffffffu, v, 4, 16);
                v += __shfl_xor_sync(0xffffffffu, v, 2, 16);
                v += __shfl_xor_sync(0xffffffffu, v, 1, 16);
                if (dq == 0) sBx[tok * 16 + n] = v;
            }
        }
    }

    // ---- Phase C: chunk scan, EMITTING every prefix (Pref_t, r_t) to global.
    {
        const int pi = tid >> 4, pj = tid & 15;
        sP[tid] = (pi == pj) ? 1.0f : 0.0f;
        if (tid < 16) sq[tid] = 0.0f;
        __syncthreads();

        float* gP = g_Pref + (size_t)c * CH * 256;
        float* gr = g_r    + (size_t)c * CH * 16;
        int cur = 0;
        for (int t = 0; t < CH; ++t) {
            const float* At = &sA[t * 256];
            float np0 = 0.0f, np1 = 0.0f;
            #pragma unroll
            for (int k = 0; k < 16; k += 2) {
                np0 += At[pi * 16 + k]     * sP[cur * 256 + k * 16 + pj];
                np1 += At[pi * 16 + k + 1] * sP[cur * 256 + (k + 1) * 16 + pj];
            }
            const float np = np0 + np1;
            float nq = 0.0f;
            if (tid < 16) {
                nq = sBx[t * 16 + tid];
                #pragma unroll
                for (int k = 0; k < 16; ++k)
                    nq += At[tid * 16 + k] * sq[cur * 16 + k];
            }
            sP[(cur ^ 1) * 256 + tid] = np;
            if (tid < 16) sq[(cur ^ 1) * 16 + tid] = nq;
            gP[t * 256 + tid] = np;                    // fire-and-forget STG
            if (tid < 16) gr[t * 16 + tid] = nq;
            cur ^= 1;
            __syncthreads();
        }
    }
}

// ---------------------------------------------------------------------------
// K2: per batch — serial scan over 64 chunk-final (P,q) pairs -> g_H0
// smem: cP[64*256] cq[64*16] = 69632 B
// ---------------------------------------------------------------------------
__global__ __launch_bounds__(256)
void k2_chain(void)
{
    extern __shared__ float sm[];
    float* cP = sm;            // 64*256
    float* cq = cP + 64 * 256; // 64*16

    const int b   = blockIdx.x;    // 0..7
    const int tid = threadIdx.x;

    for (int e = tid; e < 64 * 256; e += 256) {
        const int cc = e >> 8, el = e & 255;
        cP[e] = g_Pref[((size_t)(b * 64 + cc) * 64 + 63) * 256 + el];
    }
    for (int e = tid; e < 64 * 16; e += 256) {
        const int cc = e >> 4, el = e & 15;
        cq[e] = g_r[((size_t)(b * 64 + cc) * 64 + 63) * 16 + el];
    }
    __syncthreads();

    if (tid < 32) {
        const int i = tid & 15;
        float h = 0.0f;
        for (int cc = 0; cc < 64; ++cc) {
            if (tid < 16) g_H0[(b * 64 + cc) * 16 + i] = h;
            float acc = cq[cc * 16 + i];
            #pragma unroll
            for (int j = 0; j < 16; ++j) {
                const float hj = __shfl_sync(0xffffffffu, h, j);
                acc += cP[cc * 256 + i * 16 + j] * hj;
            }
            h = acc;
        }
    }
}

// ---------------------------------------------------------------------------
// K3: per chunk — h_t = Pref_t @ h0 + r_t (parallel), then
//     out = (x@W_C + b_C)^T h with prefetched W_C.
// smem: sx[64*68] sh[64*16] sh0[16] = 21568 B (no sA -> high occupancy)
// ---------------------------------------------------------------------------
constexpr int SXS = 68;  // padded x row stride

__global__ __launch_bounds__(256)
void k3_out(const float* __restrict__ x,
            const float* __restrict__ WC, const float* __restrict__ bC,
            float* __restrict__ out)
{
    extern __shared__ float sm[];
    float* sx  = sm;                 // 64*68
    float* sh  = sx + 64 * SXS;      // 64*16
    float* sh0 = sh + 64 * 16;       // 16

    const int c   = blockIdx.x;
    const int tid = threadIdx.x;
    const float* xc = x + (size_t)c * CH * D;

    for (int i = tid; i < CH * D; i += 256)
        sx[(i >> 6) * SXS + (i & 63)] = xc[i];
    if (tid < 16) sh0[tid] = g_H0[c * 16 + tid];
    __syncthreads();

    // h for every token, fully parallel: 4 (t,n) tasks per thread
    {
        const float* gP = g_Pref + (size_t)c * CH * 256;
        const float* gr = g_r    + (size_t)c * CH * 16;
        #pragma unroll
        for (int u = 0; u < 4; ++u) {
            const int e = tid + 256 * u;   // 0..1023
            const int t = e >> 4, n = e & 15;
            const float4* prow = (const float4*)(gP + t * 256 + n * 16);
            float acc = gr[e];
            #pragma unroll
            for (int jq = 0; jq < 4; ++jq) {
                const float4 p  = prow[jq];
                const float4 h0 = *(const float4*)&sh0[jq * 4];
                acc += p.x * h0.x + p.y * h0.y + p.z * h0.z + p.w * h0.w;
            }
            sh[e] = acc;
        }
    }
    __syncthreads();

    // output: thread owns 4 tokens x 4 d's.  dq = tid&15, tg = tid>>4
    {
        const int dq = tid & 15;
        const int tg = tid >> 4;
        const float4* WC4 = (const float4*)WC;
        float4 oacc[4];
        #pragma unroll
        for (int t = 0; t < 4; ++t) oacc[t] = make_float4(0.f, 0.f, 0.f, 0.f);

        for (int n = 0; n < 16; ++n) {
            const int widx = n * 16 + dq;
            const float4 bcn = *(const float4*)&bC[n * 64 + dq * 4];
            float4 cm[4];
            #pragma unroll
            for (int t = 0; t < 4; ++t) cm[t] = bcn;
            float4 w[4];
            #pragma unroll
            for (int j = 0; j < 4; ++j) w[j] = WC4[j * 256 + widx];
            for (int kg = 0; kg < 16; ++kg) {
                float4 wn[4];
                const int nk = (kg < 15) ? (kg + 1) * 4 : 0;
                #pragma unroll
                for (int j = 0; j < 4; ++j) wn[j] = WC4[(nk + j) * 256 + widx];
                #pragma unroll
                for (int j = 0; j < 4; ++j) {
                    const int k = kg * 4 + j;
                    #pragma unroll
                    for (int t = 0; t < 4; ++t) {
                        const float xk = sx[(tg * 4 + t) * SXS + k];
                        cm[t].x += xk * w[j].x; cm[t].y += xk * w[j].y;
                        cm[t].z += xk * w[j].z; cm[t].w += xk * w[j].w;
                    }
                }
                #pragma unroll
                for (int j = 0; j < 4; ++j) w[j] = wn[j];
            }
            #pragma unroll
            for (int t = 0; t < 4; ++t) {
                const float hn = sh[(tg * 4 + t) * 16 + n];
                oacc[t].x += hn * cm[t].x; oacc[t].y += hn * cm[t].y;
                oacc[t].z += hn * cm[t].z; oacc[t].w += hn * cm[t].w;
            }
        }
        #pragma unroll
        for (int t = 0; t < 4; ++t) {
            const int tok = tg * 4 + t;
            *(float4*)&out[((size_t)c * CH + tok) * 64 + dq * 4] = oacc[t];
        }
    }
}

// ---------------------------------------------------------------------------
extern "C" void kernel_launch(void* const* d_in, const int* in_sizes, int n_in,
                              void* d_out, int out_size)
{
    const float* x  = (const float*)d_in[0];
    const float* WA = (const float*)d_in[1];
    const float* bA = (const float*)d_in[2];
    const float* WB = (const float*)d_in[3];
    const float* bB = (const float*)d_in[4];
    const float* WC = (const float*)d_in[5];
    const float* bC = (const float*)d_in[6];
    float* out = (float*)d_out;

    const int smem1 = (64 * 64 + 64 * 256 + 64 * 16 + 512 + 32) * 4;   // 88192
    const int smem2 = (64 * 256 + 64 * 16) * 4;                        // 69632
    const int smem3 = (64 * SXS + 64 * 16 + 16) * 4;                   // 21568

    cudaFuncSetAttribute(k1_proj_scan, cudaFuncAttributeMaxDynamicSharedMemorySize, smem1);
    cudaFuncSetAttribute(k2_chain,     cudaFuncAttributeMaxDynamicSharedMemorySize, smem2);
    cudaFuncSetAttribute(k3_out,       cudaFuncAttributeMaxDynamicSharedMemorySize, smem3);

    k1_proj_scan<<<NCHUNKS, 256, smem1>>>(x, WA, bA, WB, bB);
    k2_chain    <<<B,       256, smem2>>>();
    k3_out      <<<NCHUNKS, 256, smem3>>>(x, WC, bC, out);
}

// round 10
// speedup vs baseline: 1.2952x; 1.1463x over previous
#include <cuda_runtime.h>
#include <cuda_bf16.h>
#include <cstdint>

// Problem constants
constexpr int B  = 8;
constexpr int S  = 4096;
constexpr int D  = 64;
constexpr int DS = 16;
constexpr int CH = 64;                       // chunk length (tokens)
constexpr int NCHUNKS = B * S / CH;          // 512
constexpr int NTOK = B * S;                  // 32768

constexpr int SXT = 68;                      // sxT row stride (floats), 16B-aligned rows
constexpr int SHT = 66;                      // shT row stride (floats), 8B-aligned

// Scratch
__device__ float g_Pref[NTOK * DS * DS];     // 33.5 MB per-token prefix transitions
__device__ float g_r  [NTOK * DS];           //  2  MB per-token prefix offsets
__device__ float g_H0 [NCHUNKS * DS];        // state at each chunk start

// ---------------------------------------------------------------------------
// packed f32x2 helpers (SASS FFMA2 — PTX-only path on sm_103a)
// ---------------------------------------------------------------------------
using u64 = unsigned long long;

__device__ __forceinline__ u64 pack2(float lo, float hi) {
    u64 r; asm("mov.b64 %0, {%1, %2};" : "=l"(r) : "f"(lo), "f"(hi)); return r;
}
__device__ __forceinline__ void unpack2(u64 v, float& lo, float& hi) {
    asm("mov.b64 {%0, %1}, %2;" : "=f"(lo), "=f"(hi) : "l"(v));
}
__device__ __forceinline__ u64 fma2(u64 a, u64 b, u64 c) {
    u64 d; asm("fma.rn.f32x2 %0, %1, %2, %3;" : "=l"(d) : "l"(a), "l"(b), "l"(c)); return d;
}
__device__ __forceinline__ u64 mul2(u64 a, u64 b) {
    u64 d; asm("mul.rn.f32x2 %0, %1, %2;" : "=l"(d) : "l"(a), "l"(b)); return d;
}
__device__ __forceinline__ u64 add2(u64 a, u64 b) {
    u64 d; asm("add.rn.f32x2 %0, %1, %2;" : "=l"(d) : "l"(a), "l"(b)); return d;
}

// transpose-load a 64x64 token-major x chunk into sxT[k*SXT + t]
__device__ __forceinline__ void load_xT(const float* __restrict__ xc, float* sxT, int tid) {
    for (int e = tid; e < 2048; e += 256) {
        const int k  = e & 63;
        const int tp = e >> 6;                 // token pair 0..31
        const float a = xc[(2 * tp)     * 64 + k];
        const float b = xc[(2 * tp + 1) * 64 + k];
        *(float2*)&sxT[k * SXT + 2 * tp] = make_float2(a, b);
    }
}

// ---------------------------------------------------------------------------
// K1: per chunk — A projection, Bx (both token-paired f32x2), then chunk scan
// smem: sxT[64*68] sA[64*256] sBx[64*16] sP[2*256] sq[2*16] = 89216 B
// ---------------------------------------------------------------------------
__global__ __launch_bounds__(256, 2)
void k1_proj_scan(const float* __restrict__ x,
                  const float* __restrict__ WA, const float* __restrict__ bA,
                  const float* __restrict__ WB, const float* __restrict__ bB)
{
    extern __shared__ float sm[];
    float* sxT = sm;                  // 64*68
    float* sA  = sxT + 64 * SXT;      // 64*256
    float* sBx = sA  + 64 * 256;      // 64*16
    float* sP  = sBx + 64 * 16;       // 2*256
    float* sq  = sP  + 512;           // 2*16

    const int c   = blockIdx.x;
    const int tid = threadIdx.x;
    const float* xc = x + (size_t)c * CH * D;

    load_xT(xc, sxT, tid);
    __syncthreads();

    // ---- Phase A: A = x @ W_A + b_A.  Thread owns column i; tokens paired
    //      in f32x2 lanes; depth-2 scalar weight prefetch.
    {
        const int i = tid;
        const float bias = bA[i];
        for (int half = 0; half < 2; ++half) {
            u64 acc[16];
            #pragma unroll
            for (int p = 0; p < 16; ++p) acc[p] = pack2(bias, bias);
            float w0 = WA[0 * 256 + i];
            float w1 = WA[1 * 256 + i];
            #pragma unroll 4
            for (int k = 0; k < 64; ++k) {
                const float w2 = (k < 62) ? WA[(k + 2) * 256 + i] : 0.0f;
                const u64 wp = pack2(w0, w0);
                const float* xrow = &sxT[k * SXT + half * 32];
                #pragma unroll
                for (int q = 0; q < 8; ++q) {
                    const ulonglong2 xv = *(const ulonglong2*)&xrow[q * 4];
                    acc[2 * q]     = fma2(xv.x, wp, acc[2 * q]);
                    acc[2 * q + 1] = fma2(xv.y, wp, acc[2 * q + 1]);
                }
                w0 = w1; w1 = w2;
            }
            #pragma unroll
            for (int p = 0; p < 16; ++p) {
                float lo, hi; unpack2(acc[p], lo, hi);
                const int t0 = half * 32 + 2 * p;
                sA[t0 * 256 + i]       = lo;
                sA[(t0 + 1) * 256 + i] = hi;
            }
        }
    }

    // ---- Phase B: Bx[t,n] = sum_d (x@W_B + b_B)[t,n,d] * x[t,d]
    //      n = tid>>4, dq = tid&15; 8-token tiles, token-paired f32x2.
    {
        const int n  = tid >> 4;
        const int dq = tid & 15;
        const float4 bb = *(const float4*)&bB[n * 64 + dq * 4];
        const float bbc[4] = {bb.x, bb.y, bb.z, bb.w};
        const float4* WB4 = (const float4*)WB;
        const int widx = n * 16 + dq;

        for (int tt = 0; tt < 8; ++tt) {
            const int base = tt * 8;
            u64 acc[4][4];
            #pragma unroll
            for (int p = 0; p < 4; ++p)
                #pragma unroll
                for (int cc = 0; cc < 4; ++cc) acc[p][cc] = pack2(bbc[cc], bbc[cc]);

            float4 w[4];
            #pragma unroll
            for (int j = 0; j < 4; ++j) w[j] = WB4[j * 256 + widx];
            for (int kg = 0; kg < 16; ++kg) {
                float4 wn[4];
                const int nk = (kg < 15) ? (kg + 1) * 4 : 0;
                #pragma unroll
                for (int j = 0; j < 4; ++j) wn[j] = WB4[(nk + j) * 256 + widx];
                #pragma unroll
                for (int j = 0; j < 4; ++j) {
                    const int k = kg * 4 + j;
                    const u64 wpx = pack2(w[j].x, w[j].x);
                    const u64 wpy = pack2(w[j].y, w[j].y);
                    const u64 wpz = pack2(w[j].z, w[j].z);
                    const u64 wpw = pack2(w[j].w, w[j].w);
                    const ulonglong2 xa = *(const ulonglong2*)&sxT[k * SXT + base];
                    const ulonglong2 xb = *(const ulonglong2*)&sxT[k * SXT + base + 4];
                    const u64 xp[4] = {xa.x, xa.y, xb.x, xb.y};
                    #pragma unroll
                    for (int p = 0; p < 4; ++p) {
                        acc[p][0] = fma2(xp[p], wpx, acc[p][0]);
                        acc[p][1] = fma2(xp[p], wpy, acc[p][1]);
                        acc[p][2] = fma2(xp[p], wpz, acc[p][2]);
                        acc[p][3] = fma2(xp[p], wpw, acc[p][3]);
                    }
                }
                #pragma unroll
                for (int j = 0; j < 4; ++j) w[j] = wn[j];
            }
            // epilogue: dot with x over this thread's 4 d's, reduce across dq
            #pragma unroll
            for (int p = 0; p < 4; ++p) {
                const int t0 = base + 2 * p;
                u64 xd0 = *(const u64*)&sxT[(dq * 4 + 0) * SXT + t0];
                u64 v = mul2(acc[p][0], xd0);
                #pragma unroll
                for (int cc = 1; cc < 4; ++cc) {
                    const u64 xdc = *(const u64*)&sxT[(dq * 4 + cc) * SXT + t0];
                    v = fma2(acc[p][cc], xdc, v);
                }
                v = add2(v, __shfl_xor_sync(0xffffffffu, v, 8, 16));
                v = add2(v, __shfl_xor_sync(0xffffffffu, v, 4, 16));
                v = add2(v, __shfl_xor_sync(0xffffffffu, v, 2, 16));
                v = add2(v, __shfl_xor_sync(0xffffffffu, v, 1, 16));
                if (dq == 0) {
                    float lo, hi; unpack2(v, lo, hi);
                    sBx[t0 * 16 + n]       = lo;
                    sBx[(t0 + 1) * 16 + n] = hi;
                }
            }
        }
    }

    // ---- Phase C: chunk scan, emitting every prefix (Pref_t, r_t) to global.
    {
        const int pi = tid >> 4, pj = tid & 15;
        sP[tid] = (pi == pj) ? 1.0f : 0.0f;
        if (tid < 16) sq[tid] = 0.0f;
        __syncthreads();

        float* gP = g_Pref + (size_t)c * CH * 256;
        float* gr = g_r    + (size_t)c * CH * 16;
        int cur = 0;
        for (int t = 0; t < CH; ++t) {
            const float* At = &sA[t * 256];
            float np0 = 0.0f, np1 = 0.0f;
            #pragma unroll
            for (int k = 0; k < 16; k += 2) {
                np0 += At[pi * 16 + k]     * sP[cur * 256 + k * 16 + pj];
                np1 += At[pi * 16 + k + 1] * sP[cur * 256 + (k + 1) * 16 + pj];
            }
            const float np = np0 + np1;
            float nq = 0.0f;
            if (tid < 16) {
                nq = sBx[t * 16 + tid];
                #pragma unroll
                for (int k = 0; k < 16; ++k)
                    nq += At[tid * 16 + k] * sq[cur * 16 + k];
            }
            sP[(cur ^ 1) * 256 + tid] = np;
            if (tid < 16) sq[(cur ^ 1) * 16 + tid] = nq;
            gP[t * 256 + tid] = np;                    // fire-and-forget STG
            if (tid < 16) gr[t * 16 + tid] = nq;
            cur ^= 1;
            __syncthreads();
        }
    }
}

// ---------------------------------------------------------------------------
// K2: per batch — serial scan over 64 chunk-final (P,q) pairs -> g_H0
// ---------------------------------------------------------------------------
__global__ __launch_bounds__(256)
void k2_chain(void)
{
    extern __shared__ float sm[];
    float* cP = sm;            // 64*256
    float* cq = cP + 64 * 256; // 64*16

    const int b   = blockIdx.x;
    const int tid = threadIdx.x;

    for (int e = tid; e < 64 * 256; e += 256) {
        const int cc = e >> 8, el = e & 255;
        cP[e] = g_Pref[((size_t)(b * 64 + cc) * 64 + 63) * 256 + el];
    }
    for (int e = tid; e < 64 * 16; e += 256) {
        const int cc = e >> 4, el = e & 15;
        cq[e] = g_r[((size_t)(b * 64 + cc) * 64 + 63) * 16 + el];
    }
    __syncthreads();

    if (tid < 32) {
        const int i = tid & 15;
        float h = 0.0f;
        for (int cc = 0; cc < 64; ++cc) {
            if (tid < 16) g_H0[(b * 64 + cc) * 16 + i] = h;
            float acc = cq[cc * 16 + i];
            #pragma unroll
            for (int j = 0; j < 16; ++j) {
                const float hj = __shfl_sync(0xffffffffu, h, j);
                acc += cP[cc * 256 + i * 16 + j] * hj;
            }
            h = acc;
        }
    }
}

// ---------------------------------------------------------------------------
// K3: per chunk — h_t = Pref_t @ h0 + r_t (parallel), then
//     out = (x@W_C + b_C)^T h, token-paired f32x2.
// smem: sxT[64*68] shT[16*66] sh0[16] = 21696 B
// ---------------------------------------------------------------------------
__global__ __launch_bounds__(256, 2)
void k3_out(const float* __restrict__ x,
            const float* __restrict__ WC, const float* __restrict__ bC,
            float* __restrict__ out)
{
    extern __shared__ float sm[];
    float* sxT = sm;                  // 64*68
    float* shT = sxT + 64 * SXT;      // 16*66  (shT[n*SHT + t])
    float* sh0 = shT + 16 * SHT;      // 16

    const int c   = blockIdx.x;
    const int tid = threadIdx.x;
    const float* xc = x + (size_t)c * CH * D;

    load_xT(xc, sxT, tid);
    if (tid < 16) sh0[tid] = g_H0[c * 16 + tid];
    __syncthreads();

    // h for every token, fully parallel; stored transposed shT[n][t]
    {
        const float* gP = g_Pref + (size_t)c * CH * 256;
        const float* gr = g_r    + (size_t)c * CH * 16;
        #pragma unroll
        for (int u = 0; u < 4; ++u) {
            const int e = tid + 256 * u;   // 0..1023
            const int t = e >> 4, n = e & 15;
            const float4* prow = (const float4*)(gP + t * 256 + n * 16);
            float acc = gr[e];
            #pragma unroll
            for (int jq = 0; jq < 4; ++jq) {
                const float4 p  = prow[jq];
                const float4 h0 = *(const float4*)&sh0[jq * 4];
                acc += p.x * h0.x + p.y * h0.y + p.z * h0.z + p.w * h0.w;
            }
            shT[n * SHT + t] = acc;
        }
    }
    __syncthreads();

    // output: thread owns 4 tokens (2 pairs) x 4 d's.  dq = tid&15, tg = tid>>4
    {
        const int dq = tid & 15;
        const int tg = tid >> 4;
        const int tb = tg * 4;                 // first token of this thread
        const float4* WC4 = (const float4*)WC;
        u64 oacc[2][4];
        #pragma unroll
        for (int p = 0; p < 2; ++p)
            #pragma unroll
            for (int cc = 0; cc < 4; ++cc) oacc[p][cc] = 0ull;

        for (int n = 0; n < 16; ++n) {
            const int widx = n * 16 + dq;
            const float4 bcn = *(const float4*)&bC[n * 64 + dq * 4];
            const float bcc[4] = {bcn.x, bcn.y, bcn.z, bcn.w};
            u64 cm[2][4];
            #pragma unroll
            for (int p = 0; p < 2; ++p)
                #pragma unroll
                for (int cc = 0; cc < 4; ++cc) cm[p][cc] = pack2(bcc[cc], bcc[cc]);

            float4 w[4];
            #pragma unroll
            for (int j = 0; j < 4; ++j) w[j] = WC4[j * 256 + widx];
            for (int kg = 0; kg < 16; ++kg) {
                float4 wn[4];
                const int nk = (kg < 15) ? (kg + 1) * 4 : 0;
                #pragma unroll
                for (int j = 0; j < 4; ++j) wn[j] = WC4[(nk + j) * 256 + widx];
                #pragma unroll
                for (int j = 0; j < 4; ++j) {
                    const int k = kg * 4 + j;
                    const u64 wpx = pack2(w[j].x, w[j].x);
                    const u64 wpy = pack2(w[j].y, w[j].y);
                    const u64 wpz = pack2(w[j].z, w[j].z);
                    const u64 wpw = pack2(w[j].w, w[j].w);
                    const ulonglong2 xa = *(const ulonglong2*)&sxT[k * SXT + tb];
                    const u64 xp[2] = {xa.x, xa.y};
                    #pragma unroll
                    for (int p = 0; p < 2; ++p) {
                        cm[p][0] = fma2(xp[p], wpx, cm[p][0]);
                        cm[p][1] = fma2(xp[p], wpy, cm[p][1]);
                        cm[p][2] = fma2(xp[p], wpz, cm[p][2]);
                        cm[p][3] = fma2(xp[p], wpw, cm[p][3]);
                    }
                }
                #pragma unroll
                for (int j = 0; j < 4; ++j) w[j] = wn[j];
            }
            // fold with h_n for this token pair
            #pragma unroll
            for (int p = 0; p < 2; ++p) {
                const u64 hp = *(const u64*)&shT[n * SHT + tb + 2 * p];
                #pragma unroll
                for (int cc = 0; cc < 4; ++cc)
                    oacc[p][cc] = fma2(hp, cm[p][cc], oacc[p][cc]);
            }
        }
        // store: unpack token pairs into float4 rows
        #pragma unroll
        for (int p = 0; p < 2; ++p) {
            float4 o0, o1;
            unpack2(oacc[p][0], o0.x, o1.x);
            unpack2(oacc[p][1], o0.y, o1.y);
            unpack2(oacc[p][2], o0.z, o1.z);
            unpack2(oacc[p][3], o0.w, o1.w);
            const int t0 = tb + 2 * p;
            *(float4*)&out[((size_t)c * CH + t0)     * 64 + dq * 4] = o0;
            *(float4*)&out[((size_t)c * CH + t0 + 1) * 64 + dq * 4] = o1;
        }
    }
}

// ---------------------------------------------------------------------------
extern "C" void kernel_launch(void* const* d_in, const int* in_sizes, int n_in,
                              void* d_out, int out_size)
{
    const float* x  = (const float*)d_in[0];
    const float* WA = (const float*)d_in[1];
    const float* bA = (const float*)d_in[2];
    const float* WB = (const float*)d_in[3];
    const float* bB = (const float*)d_in[4];
    const float* WC = (const float*)d_in[5];
    const float* bC = (const float*)d_in[6];
    float* out = (float*)d_out;

    const int smem1 = (64 * SXT + 64 * 256 + 64 * 16 + 512 + 32) * 4;  // 89216
    const int smem2 = (64 * 256 + 64 * 16) * 4;                        // 69632
    const int smem3 = (64 * SXT + 16 * SHT + 16) * 4;                  // 21696

    cudaFuncSetAttribute(k1_proj_scan, cudaFuncAttributeMaxDynamicSharedMemorySize, smem1);
    cudaFuncSetAttribute(k2_chain,     cudaFuncAttributeMaxDynamicSharedMemorySize, smem2);
    cudaFuncSetAttribute(k3_out,       cudaFuncAttributeMaxDynamicSharedMemorySize, smem3);

    k1_proj_scan<<<NCHUNKS, 256, smem1>>>(x, WA, bA, WB, bB);
    k2_chain    <<<B,       256, smem2>>>();
    k3_out      <<<NCHUNKS, 256, smem3>>>(x, WC, bC, out);
}